// round 1
// baseline (speedup 1.0000x reference)
#include <cuda_runtime.h>
#include <math.h>

// Problem constants
#define B_  2
#define L_  2048
#define DIM_ 2048
#define H_  16
#define HD_ 128   // head dim

// Scratch (device globals; allocation in kernel_launch is forbidden)
__device__ float g_q[(size_t)B_ * L_ * DIM_];    // (B,L,H,128) = 32 MB
__device__ float g_k[(size_t)B_ * L_ * HD_];     // (B,L,128)
__device__ float g_v[(size_t)B_ * L_ * HD_];
__device__ float g_ao[(size_t)B_ * L_ * DIM_];   // attention out, (B,L,DIM)

// ---------------------------------------------------------------------------
// SGEMM: C[M,N] = A[M,K] @ B[K,N], all row-major fp32.
// BM=128, BN=128, BK=8, 256 threads, 8x8 per-thread tile.
// Requires M%128==0, N%128==0, K%8==0.
// ---------------------------------------------------------------------------
__global__ __launch_bounds__(256) void sgemm128_kernel(
    int M, int N, int K,
    const float* __restrict__ A, const float* __restrict__ Bm,
    float* __restrict__ C)
{
    constexpr int BM = 128, BN = 128, BK = 8;
    __shared__ float As[BK][BM];
    __shared__ float Bs[BK][BN];

    const int bm = blockIdx.y * BM;
    const int bn = blockIdx.x * BN;
    const int tid = threadIdx.x;
    const int tcol = tid & 15;   // 0..15
    const int trow = tid >> 4;   // 0..15

    float acc[8][8] = {};

    const int a_row = tid >> 1;          // 0..127
    const int a_col = (tid & 1) * 4;     // 0 or 4
    const int b_row = tid >> 5;          // 0..7
    const int b_col = (tid & 31) * 4;    // 0..124

    const float* Aptr = A + (size_t)(bm + a_row) * K + a_col;
    const float* Bptr = Bm + (size_t)b_row * N + bn + b_col;

    for (int k0 = 0; k0 < K; k0 += BK) {
        float4 a4 = *(const float4*)(Aptr + k0);
        As[a_col + 0][a_row] = a4.x;
        As[a_col + 1][a_row] = a4.y;
        As[a_col + 2][a_row] = a4.z;
        As[a_col + 3][a_row] = a4.w;
        float4 b4 = *(const float4*)(Bptr + (size_t)k0 * N);
        *(float4*)&Bs[b_row][b_col] = b4;
        __syncthreads();

        #pragma unroll
        for (int kk = 0; kk < BK; ++kk) {
            float4 a0 = *(const float4*)&As[kk][trow * 4];
            float4 a1 = *(const float4*)&As[kk][64 + trow * 4];
            float4 b0 = *(const float4*)&Bs[kk][tcol * 4];
            float4 b1 = *(const float4*)&Bs[kk][64 + tcol * 4];
            float ar[8] = {a0.x, a0.y, a0.z, a0.w, a1.x, a1.y, a1.z, a1.w};
            float br[8] = {b0.x, b0.y, b0.z, b0.w, b1.x, b1.y, b1.z, b1.w};
            #pragma unroll
            for (int i = 0; i < 8; ++i)
                #pragma unroll
                for (int j = 0; j < 8; ++j)
                    acc[i][j] += ar[i] * br[j];
        }
        __syncthreads();
    }

    #pragma unroll
    for (int ih = 0; ih < 2; ++ih) {
        #pragma unroll
        for (int i = 0; i < 4; ++i) {
            const int row = bm + ih * 64 + trow * 4 + i;
            float* crow = C + (size_t)row * N + bn;
            float4 c0 = {acc[ih*4+i][0], acc[ih*4+i][1], acc[ih*4+i][2], acc[ih*4+i][3]};
            float4 c1 = {acc[ih*4+i][4], acc[ih*4+i][5], acc[ih*4+i][6], acc[ih*4+i][7]};
            *(float4*)(crow + tcol * 4) = c0;
            *(float4*)(crow + 64 + tcol * 4) = c1;
        }
    }
}

// ---------------------------------------------------------------------------
// Skinny SGEMM for N=128: BM=32, BN=128, BK=16, 128 threads, 4x8 per thread.
// Gives 128 blocks for the K/V projections instead of 32.
// ---------------------------------------------------------------------------
__global__ __launch_bounds__(128) void sgemm_skinny_kernel(
    int M, int N, int K,
    const float* __restrict__ A, const float* __restrict__ Bm,
    float* __restrict__ C)
{
    constexpr int BM = 32, BN = 128, BK = 16;
    __shared__ float As[BK][BM];
    __shared__ float Bs[BK][BN];

    const int bm = blockIdx.y * BM;
    const int bn = blockIdx.x * BN;
    const int tid = threadIdx.x;    // 0..127
    const int tcol = tid & 15;      // 0..15
    const int trow = tid >> 4;      // 0..7

    float acc[4][8] = {};

    const int a_row = tid >> 2;         // 0..31
    const int a_col = (tid & 3) * 4;    // 0..12
    const int b_row0 = tid >> 5;        // 0..3
    const int b_col = (tid & 31) * 4;   // 0..124

    const float* Aptr = A + (size_t)(bm + a_row) * K + a_col;

    for (int k0 = 0; k0 < K; k0 += BK) {
        float4 a4 = *(const float4*)(Aptr + k0);
        As[a_col + 0][a_row] = a4.x;
        As[a_col + 1][a_row] = a4.y;
        As[a_col + 2][a_row] = a4.z;
        As[a_col + 3][a_row] = a4.w;
        #pragma unroll
        for (int p = 0; p < 4; ++p) {
            int br = b_row0 + p * 4;
            float4 b4 = *(const float4*)(Bm + (size_t)(k0 + br) * N + bn + b_col);
            *(float4*)&Bs[br][b_col] = b4;
        }
        __syncthreads();

        #pragma unroll
        for (int kk = 0; kk < BK; ++kk) {
            float4 a0 = *(const float4*)&As[kk][trow * 4];
            float4 b0 = *(const float4*)&Bs[kk][tcol * 4];
            float4 b1 = *(const float4*)&Bs[kk][64 + tcol * 4];
            float ar[4] = {a0.x, a0.y, a0.z, a0.w};
            float br[8] = {b0.x, b0.y, b0.z, b0.w, b1.x, b1.y, b1.z, b1.w};
            #pragma unroll
            for (int i = 0; i < 4; ++i)
                #pragma unroll
                for (int j = 0; j < 8; ++j)
                    acc[i][j] += ar[i] * br[j];
        }
        __syncthreads();
    }

    #pragma unroll
    for (int i = 0; i < 4; ++i) {
        const int row = bm + trow * 4 + i;
        float* crow = C + (size_t)row * N + bn;
        float4 c0 = {acc[i][0], acc[i][1], acc[i][2], acc[i][3]};
        float4 c1 = {acc[i][4], acc[i][5], acc[i][6], acc[i][7]};
        *(float4*)(crow + tcol * 4) = c0;
        *(float4*)(crow + 64 + tcol * 4) = c1;
    }
}

// ---------------------------------------------------------------------------
// Fused RoPE + RMSNorm, in place. One warp per 128-dim vector.
// vecs_per_token: 16 for q (B,L,H,128 layout), 1 for k (B,L,128).
// ---------------------------------------------------------------------------
__global__ __launch_bounds__(256) void rope_rms_kernel(
    float* __restrict__ v, const float* __restrict__ cosb,
    const float* __restrict__ sinb, int vecs_per_token)
{
    const int warp = (blockIdx.x * blockDim.x + threadIdx.x) >> 5;
    const int lane = threadIdx.x & 31;
    const int l = (warp / vecs_per_token) % L_;

    float* p = v + (size_t)warp * HD_;
    float e0 = p[lane];
    float e1 = p[lane + 32];
    float e2 = p[lane + 64];
    float e3 = p[lane + 96];
    float c0 = cosb[l * 64 + lane];
    float s0 = sinb[l * 64 + lane];
    float c1 = cosb[l * 64 + lane + 32];
    float s1 = sinb[l * 64 + lane + 32];

    // rope: out[j] = x1*c + x2*s ; out[64+j] = -x1*s + x2*c
    float r0 =  e0 * c0 + e2 * s0;
    float r2 = -e0 * s0 + e2 * c0;
    float r1 =  e1 * c1 + e3 * s1;
    float r3 = -e1 * s1 + e3 * c1;

    float ss = r0 * r0 + r1 * r1 + r2 * r2 + r3 * r3;
    #pragma unroll
    for (int o = 16; o; o >>= 1) ss += __shfl_xor_sync(0xffffffffu, ss, o);
    float sc = rsqrtf(ss * (1.0f / 128.0f) + 1e-6f);

    p[lane]      = r0 * sc;
    p[lane + 32] = r1 * sc;
    p[lane + 64] = r2 * sc;
    p[lane + 96] = r3 * sc;
}

// ---------------------------------------------------------------------------
// Flash attention (causal, MQA). One block = (q-tile of 64, head, batch).
// 256 threads = 16x16. Causal tile skipping. fp32 throughout.
// ---------------------------------------------------------------------------
#define BQ 64
#define BKT 64
#define QS_STRIDE 132
#define SS_STRIDE 65
#define FLASH_SMEM_FLOATS (BQ*QS_STRIDE + HD_*BKT + BKT*HD_ + BQ*SS_STRIDE + 3*BQ)

__global__ __launch_bounds__(256) void flash_attn_kernel(
    const float* __restrict__ Q, const float* __restrict__ Kg,
    const float* __restrict__ Vg, float* __restrict__ Og)
{
    extern __shared__ float sm[];
    float* Qs   = sm;                        // BQ x 132 (row stride 132)
    float* Kst  = Qs + BQ * QS_STRIDE;       // 128 x 64 (transposed K tile)
    float* Vs   = Kst + HD_ * BKT;           // 64 x 128
    float* Ss   = Vs + BKT * HD_;            // 64 x 65
    float* mrow = Ss + BQ * SS_STRIDE;       // 64
    float* lrow = mrow + BQ;                 // 64
    float* arow = lrow + BQ;                 // 64

    const int q0 = blockIdx.x * BQ;
    const int h  = blockIdx.y;
    const int b  = blockIdx.z;
    const int tid = threadIdx.x;
    const int tx = tid & 15;
    const int ty = tid >> 4;

    // Load Q tile (64 x 128), layout (B,L,H,128)
    for (int i = tid; i < BQ * HD_ / 4; i += 256) {
        int r = i >> 5, c4 = (i & 31) << 2;
        float4 v = *(const float4*)&Q[(((size_t)b * L_ + q0 + r) * H_ + h) * HD_ + c4];
        *(float4*)&Qs[r * QS_STRIDE + c4] = v;
    }
    if (tid < BQ) { mrow[tid] = -1e30f; lrow[tid] = 0.f; }
    __syncthreads();

    float o[4][8] = {};
    const float scale = 0.08838834764831843f; // 1/sqrt(128)
    const int ntiles = q0 / BKT + 1;          // causal skip

    for (int t = 0; t < ntiles; ++t) {
        const int k0 = t * BKT;
        // Load K (transposed into Kst[d][r]) and V (row-major)
        for (int i = tid; i < BKT * HD_ / 4; i += 256) {
            int r = i >> 5, c4 = (i & 31) << 2;
            float4 kv = *(const float4*)&Kg[((size_t)b * L_ + k0 + r) * HD_ + c4];
            Kst[(c4 + 0) * BKT + r] = kv.x;
            Kst[(c4 + 1) * BKT + r] = kv.y;
            Kst[(c4 + 2) * BKT + r] = kv.z;
            Kst[(c4 + 3) * BKT + r] = kv.w;
            float4 vv = *(const float4*)&Vg[((size_t)b * L_ + k0 + r) * HD_ + c4];
            *(float4*)&Vs[r * HD_ + c4] = vv;
        }
        __syncthreads();

        // S = Q K^T (4x4 per thread)
        float s[4][4] = {};
        for (int d = 0; d < HD_; ++d) {
            float4 kr = *(const float4*)&Kst[d * BKT + tx * 4];
            float q0v = Qs[(ty * 4 + 0) * QS_STRIDE + d];
            float q1v = Qs[(ty * 4 + 1) * QS_STRIDE + d];
            float q2v = Qs[(ty * 4 + 2) * QS_STRIDE + d];
            float q3v = Qs[(ty * 4 + 3) * QS_STRIDE + d];
            s[0][0] += q0v * kr.x; s[0][1] += q0v * kr.y; s[0][2] += q0v * kr.z; s[0][3] += q0v * kr.w;
            s[1][0] += q1v * kr.x; s[1][1] += q1v * kr.y; s[1][2] += q1v * kr.z; s[1][3] += q1v * kr.w;
            s[2][0] += q2v * kr.x; s[2][1] += q2v * kr.y; s[2][2] += q2v * kr.z; s[2][3] += q2v * kr.w;
            s[3][0] += q3v * kr.x; s[3][1] += q3v * kr.y; s[3][2] += q3v * kr.z; s[3][3] += q3v * kr.w;
        }

        // mask + write S to smem
        #pragma unroll
        for (int i = 0; i < 4; ++i) {
            const int qi = q0 + ty * 4 + i;
            #pragma unroll
            for (int j = 0; j < 4; ++j) {
                const int kj = k0 + tx * 4 + j;
                Ss[(ty * 4 + i) * SS_STRIDE + tx * 4 + j] =
                    (kj <= qi) ? s[i][j] * scale : -1e30f;
            }
        }
        __syncthreads();

        // online softmax per row (64 rows by first 64 threads)
        if (tid < BQ) {
            float m_old = mrow[tid];
            float mx = m_old;
            #pragma unroll 4
            for (int j = 0; j < BKT; ++j) mx = fmaxf(mx, Ss[tid * SS_STRIDE + j]);
            float sum = 0.f;
            #pragma unroll 4
            for (int j = 0; j < BKT; ++j) {
                float pv = __expf(Ss[tid * SS_STRIDE + j] - mx);
                Ss[tid * SS_STRIDE + j] = pv;
                sum += pv;
            }
            float alpha = __expf(m_old - mx);
            lrow[tid] = lrow[tid] * alpha + sum;
            mrow[tid] = mx;
            arow[tid] = alpha;
        }
        __syncthreads();

        // O = O*alpha + P @ V
        #pragma unroll
        for (int i = 0; i < 4; ++i) {
            float alpha = arow[ty * 4 + i];
            #pragma unroll
            for (int j = 0; j < 8; ++j) o[i][j] *= alpha;
        }
        for (int kk = 0; kk < BKT; ++kk) {
            float4 v0 = *(const float4*)&Vs[kk * HD_ + tx * 4];
            float4 v1 = *(const float4*)&Vs[kk * HD_ + 64 + tx * 4];
            #pragma unroll
            for (int i = 0; i < 4; ++i) {
                float pv = Ss[(ty * 4 + i) * SS_STRIDE + kk];
                o[i][0] += pv * v0.x; o[i][1] += pv * v0.y;
                o[i][2] += pv * v0.z; o[i][3] += pv * v0.w;
                o[i][4] += pv * v1.x; o[i][5] += pv * v1.y;
                o[i][6] += pv * v1.z; o[i][7] += pv * v1.w;
            }
        }
        __syncthreads();
    }

    // normalize and store to (B,L,DIM) with head-major columns
    #pragma unroll
    for (int i = 0; i < 4; ++i) {
        const int row = q0 + ty * 4 + i;
        const float inv = 1.f / lrow[ty * 4 + i];
        float4 r0 = {o[i][0]*inv, o[i][1]*inv, o[i][2]*inv, o[i][3]*inv};
        float4 r1 = {o[i][4]*inv, o[i][5]*inv, o[i][6]*inv, o[i][7]*inv};
        size_t base = ((size_t)b * L_ + row) * DIM_ + (size_t)h * HD_;
        *(float4*)&Og[base + tx * 4] = r0;
        *(float4*)&Og[base + 64 + tx * 4] = r1;
    }
}

// ---------------------------------------------------------------------------
extern "C" void kernel_launch(void* const* d_in, const int* in_sizes, int n_in,
                              void* d_out, int out_size)
{
    const float* x    = (const float*)d_in[0]; // (B,L,DIM)
    const float* cosb = (const float*)d_in[1]; // (L,1,64)
    const float* sinb = (const float*)d_in[2];
    const float* Wq   = (const float*)d_in[3]; // (DIM,DIM)
    const float* Wk   = (const float*)d_in[4]; // (DIM,128)
    const float* Wv   = (const float*)d_in[5];
    const float* Wo   = (const float*)d_in[6]; // (DIM,DIM)
    float* out = (float*)d_out;

    float *qp, *kp, *vp, *aop;
    cudaGetSymbolAddress((void**)&qp, g_q);
    cudaGetSymbolAddress((void**)&kp, g_k);
    cudaGetSymbolAddress((void**)&vp, g_v);
    cudaGetSymbolAddress((void**)&aop, g_ao);

    const int M = B_ * L_;   // 4096

    // 1) Q projection: (4096,2048) @ (2048,2048)
    sgemm128_kernel<<<dim3(DIM_ / 128, M / 128), 256>>>(M, DIM_, DIM_, x, Wq, qp);
    // 2) K,V projections: (4096,2048) @ (2048,128)
    sgemm_skinny_kernel<<<dim3(1, M / 32), 128>>>(M, HD_, DIM_, x, Wk, kp);
    sgemm_skinny_kernel<<<dim3(1, M / 32), 128>>>(M, HD_, DIM_, x, Wv, vp);

    // 3) RoPE + RMSNorm (in place)
    rope_rms_kernel<<<(M * H_) * 32 / 256, 256>>>(qp, cosb, sinb, H_);
    rope_rms_kernel<<<M * 32 / 256, 256>>>(kp, cosb, sinb, 1);

    // 4) causal MQA flash attention
    const size_t smem = FLASH_SMEM_FLOATS * sizeof(float);
    cudaFuncSetAttribute(flash_attn_kernel,
                         cudaFuncAttributeMaxDynamicSharedMemorySize, (int)smem);
    flash_attn_kernel<<<dim3(L_ / BQ, H_, B_), 256, smem>>>(qp, kp, vp, aop);

    // 5) output projection: (4096,2048) @ (2048,2048)
    sgemm128_kernel<<<dim3(DIM_ / 128, M / 128), 256>>>(M, DIM_, DIM_, aop, Wo, out);
}

// round 3
// speedup vs baseline: 1.3421x; 1.3421x over previous
#include <cuda_runtime.h>
#include <cstdint>
#include <math.h>

// Problem constants
#define B_  2
#define L_  2048
#define DIM_ 2048
#define H_  16
#define HD_ 128   // head dim

// ---------------------------------------------------------------------------
// Scratch (device globals; allocation in kernel_launch is forbidden)
// ---------------------------------------------------------------------------
__device__ float g_q[(size_t)B_ * L_ * DIM_];    // (B,L,H,128)
__device__ float g_k[(size_t)B_ * L_ * HD_];     // (B,L,128)
__device__ float g_v[(size_t)B_ * L_ * HD_];
__device__ float g_ao[(size_t)B_ * L_ * DIM_];   // attention out
__device__ float g_wqt[(size_t)DIM_ * DIM_];     // Wq^T  [N][K]
__device__ float g_wot[(size_t)DIM_ * DIM_];     // Wo^T
__device__ float g_wkt[(size_t)HD_ * DIM_];      // Wk^T  [128][2048]
__device__ float g_wvt[(size_t)HD_ * DIM_];

// ---------------------------------------------------------------------------
__device__ __forceinline__ float tf32_rna(float v) {
    float o;
    asm("cvt.rna.tf32.f32 %0, %1;" : "=f"(o) : "f"(v));
    return o;
}

// mma.sync m16n8k8 tf32: d += a * b  (family-neutral, works on sm_103)
__device__ __forceinline__ void mma_tf32(float* d,
    float a0, float a1, float a2, float a3, float b0, float b1)
{
    asm volatile(
        "mma.sync.aligned.m16n8k8.row.col.f32.tf32.tf32.f32 "
        "{%0,%1,%2,%3}, {%4,%5,%6,%7}, {%8,%9}, {%0,%1,%2,%3};"
        : "+f"(d[0]), "+f"(d[1]), "+f"(d[2]), "+f"(d[3])
        : "r"(__float_as_uint(a0)), "r"(__float_as_uint(a1)),
          "r"(__float_as_uint(a2)), "r"(__float_as_uint(a3)),
          "r"(__float_as_uint(b0)), "r"(__float_as_uint(b1)));
}

// ---------------------------------------------------------------------------
// Transpose: out[C][R] = in[R][C]
// ---------------------------------------------------------------------------
__global__ __launch_bounds__(256) void transpose_kernel(
    const float* __restrict__ in, float* __restrict__ out, int R, int C)
{
    __shared__ float t[32][33];
    const int c0 = blockIdx.x * 32, r0 = blockIdx.y * 32;
    const int x = threadIdx.x, y = threadIdx.y;  // 32 x 8
    #pragma unroll
    for (int i = 0; i < 32; i += 8)
        t[y + i][x] = in[(size_t)(r0 + y + i) * C + c0 + x];
    __syncthreads();
    #pragma unroll
    for (int i = 0; i < 32; i += 8)
        out[(size_t)(c0 + y + i) * R + r0 + x] = t[x][y + i];
}

// ---------------------------------------------------------------------------
// tf32 mma.sync GEMM: C[M,N] = A[M,K] @ Bt[N,K]^T
// BM=BN=128, BK=32. 256 threads = 8 warps (4 x 2), warp tile 32x64.
// Smem layout per tile row (32 floats): k-group j (8 cols), col 8j+c stored at
// float index 8j + 2*(c&3) + (c>>2)  -> (c, c+4) become an adjacent float2,
// matching tf32 m16n8k8 fragment pairs. Row stride 36 floats (pad).
// ---------------------------------------------------------------------------
#define GEMM_BUF_FLOATS (128 * 36)
#define GEMM_SMEM_BYTES (4 * GEMM_BUF_FLOATS * 4)   // A0,A1,B0,B1

__global__ __launch_bounds__(256) void gemm_tf32_mma_kernel(
    int M, int N, int K,
    const float* __restrict__ A, const float* __restrict__ Bt,
    float* __restrict__ C)
{
    extern __shared__ float sm[];
    float* sA = sm;                          // [2][128*36]
    float* sB = sm + 2 * GEMM_BUF_FLOATS;    // [2][128*36]

    const int tid  = threadIdx.x;
    const int wid  = tid >> 5, lane = tid & 31;
    const int tig  = lane & 3, grp = lane >> 2;
    const int wm   = wid & 3;        // 0..3 -> 32 rows each
    const int wn   = wid >> 2;       // 0..1 -> 64 cols each
    const int bm   = blockIdx.y * 128, bn = blockIdx.x * 128;

    float acc[2][8][4];
    #pragma unroll
    for (int mt = 0; mt < 2; ++mt)
        #pragma unroll
        for (int nt = 0; nt < 8; ++nt)
            #pragma unroll
            for (int e = 0; e < 4; ++e) acc[mt][nt][e] = 0.f;

    // loader indices: 1024 float4 per tile, 4 per thread
    const int lrow = tid >> 3;             // 0..31 (with +32*p)
    const int lc4  = (tid & 7) * 4;        // 0,4,...,28
    const int slot = 8 * (lc4 >> 3) + ((lc4 >> 2) & 1);  // base float slot

    float4 ra[4], rb[4];

    auto gload = [&](int it) {
        const int k0 = it * 32;
        #pragma unroll
        for (int p = 0; p < 4; ++p) {
            const int row = lrow + p * 32;
            ra[p] = *(const float4*)&A [(size_t)(bm + row) * K + k0 + lc4];
            rb[p] = *(const float4*)&Bt[(size_t)(bn + row) * K + k0 + lc4];
        }
    };
    auto sstore = [&](int buf) {
        float* dA = sA + buf * GEMM_BUF_FLOATS;
        float* dB = sB + buf * GEMM_BUF_FLOATS;
        #pragma unroll
        for (int p = 0; p < 4; ++p) {
            const int row = lrow + p * 32;
            float* pa = dA + row * 36 + slot;
            pa[0] = tf32_rna(ra[p].x); pa[2] = tf32_rna(ra[p].y);
            pa[4] = tf32_rna(ra[p].z); pa[6] = tf32_rna(ra[p].w);
            float* pb = dB + row * 36 + slot;
            pb[0] = tf32_rna(rb[p].x); pb[2] = tf32_rna(rb[p].y);
            pb[4] = tf32_rna(rb[p].z); pb[6] = tf32_rna(rb[p].w);
        }
    };

    const int NIT = K / 32;
    gload(0);
    sstore(0);

    for (int it = 0; it < NIT; ++it) {
        __syncthreads();
        if (it + 1 < NIT) gload(it + 1);

        const float* cA = sA + (it & 1) * GEMM_BUF_FLOATS;
        const float* cB = sB + (it & 1) * GEMM_BUF_FLOATS;
        #pragma unroll
        for (int j = 0; j < 4; ++j) {
            float2 af[2][2];
            #pragma unroll
            for (int mt = 0; mt < 2; ++mt) {
                const int r = wm * 32 + mt * 16 + grp;
                af[mt][0] = *(const float2*)&cA[r * 36 + 8 * j + 2 * tig];
                af[mt][1] = *(const float2*)&cA[(r + 8) * 36 + 8 * j + 2 * tig];
            }
            float2 bf[8];
            #pragma unroll
            for (int nt = 0; nt < 8; ++nt) {
                const int n = wn * 64 + nt * 8 + grp;
                bf[nt] = *(const float2*)&cB[n * 36 + 8 * j + 2 * tig];
            }
            #pragma unroll
            for (int mt = 0; mt < 2; ++mt)
                #pragma unroll
                for (int nt = 0; nt < 8; ++nt)
                    mma_tf32(acc[mt][nt],
                             af[mt][0].x, af[mt][1].x, af[mt][0].y, af[mt][1].y,
                             bf[nt].x, bf[nt].y);
        }

        if (it + 1 < NIT) {
            __syncthreads();
            sstore((it + 1) & 1);
        }
    }

    // epilogue
    #pragma unroll
    for (int mt = 0; mt < 2; ++mt) {
        const int m = bm + wm * 32 + mt * 16 + grp;
        #pragma unroll
        for (int nt = 0; nt < 8; ++nt) {
            const int n = bn + wn * 64 + nt * 8 + 2 * tig;
            float2 lo = {acc[mt][nt][0], acc[mt][nt][1]};
            float2 hi = {acc[mt][nt][2], acc[mt][nt][3]};
            *(float2*)&C[(size_t)m * N + n] = lo;
            *(float2*)&C[(size_t)(m + 8) * N + n] = hi;
        }
    }
}

// ---------------------------------------------------------------------------
// Fused RoPE + RMSNorm, in place. One warp per 128-dim vector.
// ---------------------------------------------------------------------------
__global__ __launch_bounds__(256) void rope_rms_kernel(
    float* __restrict__ v, const float* __restrict__ cosb,
    const float* __restrict__ sinb, int vecs_per_token)
{
    const int warp = (blockIdx.x * blockDim.x + threadIdx.x) >> 5;
    const int lane = threadIdx.x & 31;
    const int l = (warp / vecs_per_token) % L_;

    float* p = v + (size_t)warp * HD_;
    float e0 = p[lane];
    float e1 = p[lane + 32];
    float e2 = p[lane + 64];
    float e3 = p[lane + 96];
    float c0 = cosb[l * 64 + lane];
    float s0 = sinb[l * 64 + lane];
    float c1 = cosb[l * 64 + lane + 32];
    float s1 = sinb[l * 64 + lane + 32];

    float r0 =  e0 * c0 + e2 * s0;
    float r2 = -e0 * s0 + e2 * c0;
    float r1 =  e1 * c1 + e3 * s1;
    float r3 = -e1 * s1 + e3 * c1;

    float ss = r0 * r0 + r1 * r1 + r2 * r2 + r3 * r3;
    #pragma unroll
    for (int o = 16; o; o >>= 1) ss += __shfl_xor_sync(0xffffffffu, ss, o);
    float sc = rsqrtf(ss * (1.0f / 128.0f) + 1e-6f);

    p[lane]      = r0 * sc;
    p[lane + 32] = r1 * sc;
    p[lane + 64] = r2 * sc;
    p[lane + 96] = r3 * sc;
}

// ---------------------------------------------------------------------------
// Flash attention (causal, MQA), fp32 SIMT.
// ---------------------------------------------------------------------------
#define BQ 64
#define BKT 64
#define QS_STRIDE 132
#define SS_STRIDE 65
#define FLASH_SMEM_FLOATS (BQ*QS_STRIDE + HD_*BKT + BKT*HD_ + BQ*SS_STRIDE + 3*BQ)

__global__ __launch_bounds__(256) void flash_attn_kernel(
    const float* __restrict__ Q, const float* __restrict__ Kg,
    const float* __restrict__ Vg, float* __restrict__ Og)
{
    extern __shared__ float sm[];
    float* Qs   = sm;
    float* Kst  = Qs + BQ * QS_STRIDE;
    float* Vs   = Kst + HD_ * BKT;
    float* Ss   = Vs + BKT * HD_;
    float* mrow = Ss + BQ * SS_STRIDE;
    float* lrow = mrow + BQ;
    float* arow = lrow + BQ;

    const int q0 = blockIdx.x * BQ;
    const int h  = blockIdx.y;
    const int b  = blockIdx.z;
    const int tid = threadIdx.x;
    const int tx = tid & 15;
    const int ty = tid >> 4;

    for (int i = tid; i < BQ * HD_ / 4; i += 256) {
        int r = i >> 5, c4 = (i & 31) << 2;
        float4 v = *(const float4*)&Q[(((size_t)b * L_ + q0 + r) * H_ + h) * HD_ + c4];
        *(float4*)&Qs[r * QS_STRIDE + c4] = v;
    }
    if (tid < BQ) { mrow[tid] = -1e30f; lrow[tid] = 0.f; }
    __syncthreads();

    float o[4][8] = {};
    const float scale = 0.08838834764831843f;
    const int ntiles = q0 / BKT + 1;

    for (int t = 0; t < ntiles; ++t) {
        const int k0 = t * BKT;
        for (int i = tid; i < BKT * HD_ / 4; i += 256) {
            int r = i >> 5, c4 = (i & 31) << 2;
            float4 kv = *(const float4*)&Kg[((size_t)b * L_ + k0 + r) * HD_ + c4];
            Kst[(c4 + 0) * BKT + r] = kv.x;
            Kst[(c4 + 1) * BKT + r] = kv.y;
            Kst[(c4 + 2) * BKT + r] = kv.z;
            Kst[(c4 + 3) * BKT + r] = kv.w;
            float4 vv = *(const float4*)&Vg[((size_t)b * L_ + k0 + r) * HD_ + c4];
            *(float4*)&Vs[r * HD_ + c4] = vv;
        }
        __syncthreads();

        float s[4][4] = {};
        for (int d = 0; d < HD_; ++d) {
            float4 kr = *(const float4*)&Kst[d * BKT + tx * 4];
            float q0v = Qs[(ty * 4 + 0) * QS_STRIDE + d];
            float q1v = Qs[(ty * 4 + 1) * QS_STRIDE + d];
            float q2v = Qs[(ty * 4 + 2) * QS_STRIDE + d];
            float q3v = Qs[(ty * 4 + 3) * QS_STRIDE + d];
            s[0][0] += q0v * kr.x; s[0][1] += q0v * kr.y; s[0][2] += q0v * kr.z; s[0][3] += q0v * kr.w;
            s[1][0] += q1v * kr.x; s[1][1] += q1v * kr.y; s[1][2] += q1v * kr.z; s[1][3] += q1v * kr.w;
            s[2][0] += q2v * kr.x; s[2][1] += q2v * kr.y; s[2][2] += q2v * kr.z; s[2][3] += q2v * kr.w;
            s[3][0] += q3v * kr.x; s[3][1] += q3v * kr.y; s[3][2] += q3v * kr.z; s[3][3] += q3v * kr.w;
        }

        #pragma unroll
        for (int i = 0; i < 4; ++i) {
            const int qi = q0 + ty * 4 + i;
            #pragma unroll
            for (int j = 0; j < 4; ++j) {
                const int kj = k0 + tx * 4 + j;
                Ss[(ty * 4 + i) * SS_STRIDE + tx * 4 + j] =
                    (kj <= qi) ? s[i][j] * scale : -1e30f;
            }
        }
        __syncthreads();

        if (tid < BQ) {
            float m_old = mrow[tid];
            float mx = m_old;
            #pragma unroll 4
            for (int j = 0; j < BKT; ++j) mx = fmaxf(mx, Ss[tid * SS_STRIDE + j]);
            float sum = 0.f;
            #pragma unroll 4
            for (int j = 0; j < BKT; ++j) {
                float pv = __expf(Ss[tid * SS_STRIDE + j] - mx);
                Ss[tid * SS_STRIDE + j] = pv;
                sum += pv;
            }
            float alpha = __expf(m_old - mx);
            lrow[tid] = lrow[tid] * alpha + sum;
            mrow[tid] = mx;
            arow[tid] = alpha;
        }
        __syncthreads();

        #pragma unroll
        for (int i = 0; i < 4; ++i) {
            float alpha = arow[ty * 4 + i];
            #pragma unroll
            for (int j = 0; j < 8; ++j) o[i][j] *= alpha;
        }
        for (int kk = 0; kk < BKT; ++kk) {
            float4 v0 = *(const float4*)&Vs[kk * HD_ + tx * 4];
            float4 v1 = *(const float4*)&Vs[kk * HD_ + 64 + tx * 4];
            #pragma unroll
            for (int i = 0; i < 4; ++i) {
                float pv = Ss[(ty * 4 + i) * SS_STRIDE + kk];
                o[i][0] += pv * v0.x; o[i][1] += pv * v0.y;
                o[i][2] += pv * v0.z; o[i][3] += pv * v0.w;
                o[i][4] += pv * v1.x; o[i][5] += pv * v1.y;
                o[i][6] += pv * v1.z; o[i][7] += pv * v1.w;
            }
        }
        __syncthreads();
    }

    #pragma unroll
    for (int i = 0; i < 4; ++i) {
        const int row = q0 + ty * 4 + i;
        const float inv = 1.f / lrow[ty * 4 + i];
        float4 r0 = {o[i][0]*inv, o[i][1]*inv, o[i][2]*inv, o[i][3]*inv};
        float4 r1 = {o[i][4]*inv, o[i][5]*inv, o[i][6]*inv, o[i][7]*inv};
        size_t base = ((size_t)b * L_ + row) * DIM_ + (size_t)h * HD_;
        *(float4*)&Og[base + tx * 4] = r0;
        *(float4*)&Og[base + 64 + tx * 4] = r1;
    }
}

// ---------------------------------------------------------------------------
extern "C" void kernel_launch(void* const* d_in, const int* in_sizes, int n_in,
                              void* d_out, int out_size)
{
    const float* x    = (const float*)d_in[0];
    const float* cosb = (const float*)d_in[1];
    const float* sinb = (const float*)d_in[2];
    const float* Wq   = (const float*)d_in[3];
    const float* Wk   = (const float*)d_in[4];
    const float* Wv   = (const float*)d_in[5];
    const float* Wo   = (const float*)d_in[6];
    float* out = (float*)d_out;

    float *qp, *kp, *vp, *aop, *wqt, *wot, *wkt, *wvt;
    cudaGetSymbolAddress((void**)&qp, g_q);
    cudaGetSymbolAddress((void**)&kp, g_k);
    cudaGetSymbolAddress((void**)&vp, g_v);
    cudaGetSymbolAddress((void**)&aop, g_ao);
    cudaGetSymbolAddress((void**)&wqt, g_wqt);
    cudaGetSymbolAddress((void**)&wot, g_wot);
    cudaGetSymbolAddress((void**)&wkt, g_wkt);
    cudaGetSymbolAddress((void**)&wvt, g_wvt);

    const int M = B_ * L_;   // 4096

    cudaFuncSetAttribute(gemm_tf32_mma_kernel,
                         cudaFuncAttributeMaxDynamicSharedMemorySize, GEMM_SMEM_BYTES);

    // 0) transpose weights to [N][K]
    transpose_kernel<<<dim3(DIM_/32, DIM_/32), dim3(32,8)>>>(Wq, wqt, DIM_, DIM_);
    transpose_kernel<<<dim3(HD_/32,  DIM_/32), dim3(32,8)>>>(Wk, wkt, DIM_, HD_);
    transpose_kernel<<<dim3(HD_/32,  DIM_/32), dim3(32,8)>>>(Wv, wvt, DIM_, HD_);
    transpose_kernel<<<dim3(DIM_/32, DIM_/32), dim3(32,8)>>>(Wo, wot, DIM_, DIM_);

    // 1) projections via mma.sync tf32
    gemm_tf32_mma_kernel<<<dim3(DIM_/128, M/128), 256, GEMM_SMEM_BYTES>>>(M, DIM_, DIM_, x, wqt, qp);
    gemm_tf32_mma_kernel<<<dim3(1,        M/128), 256, GEMM_SMEM_BYTES>>>(M, HD_,  DIM_, x, wkt, kp);
    gemm_tf32_mma_kernel<<<dim3(1,        M/128), 256, GEMM_SMEM_BYTES>>>(M, HD_,  DIM_, x, wvt, vp);

    // 2) RoPE + RMSNorm
    rope_rms_kernel<<<(M * H_) * 32 / 256, 256>>>(qp, cosb, sinb, H_);
    rope_rms_kernel<<<M * 32 / 256, 256>>>(kp, cosb, sinb, 1);

    // 3) causal MQA flash attention (fp32 SIMT)
    const size_t smem = FLASH_SMEM_FLOATS * sizeof(float);
    cudaFuncSetAttribute(flash_attn_kernel,
                         cudaFuncAttributeMaxDynamicSharedMemorySize, (int)smem);
    flash_attn_kernel<<<dim3(L_ / BQ, H_, B_), 256, smem>>>(qp, kp, vp, aop);

    // 4) output projection
    gemm_tf32_mma_kernel<<<dim3(DIM_/128, M/128), 256, GEMM_SMEM_BYTES>>>(M, DIM_, DIM_, aop, wot, out);
}

// round 4
// speedup vs baseline: 1.3426x; 1.0004x over previous
#include <cuda_runtime.h>
#include <cstdint>
#include <math.h>

// Problem constants
#define B_  2
#define L_  2048
#define DIM_ 2048
#define H_  16
#define HD_ 128   // head dim

// ---------------------------------------------------------------------------
// Scratch (device globals; allocation in kernel_launch is forbidden)
// ---------------------------------------------------------------------------
__device__ float g_q[(size_t)B_ * L_ * DIM_];    // (B,L,H,128)
__device__ float g_k[(size_t)B_ * L_ * HD_];     // (B,L,128)
__device__ float g_v[(size_t)B_ * L_ * HD_];
__device__ float g_ao[(size_t)B_ * L_ * DIM_];   // attention out
__device__ float g_wqt[(size_t)DIM_ * DIM_];     // Wq^T  [N][K]
__device__ float g_wot[(size_t)DIM_ * DIM_];     // Wo^T
__device__ float g_wkt[(size_t)HD_ * DIM_];      // Wk^T  [128][2048]
__device__ float g_wvt[(size_t)HD_ * DIM_];

// ---------------------------------------------------------------------------
__device__ __forceinline__ float tf32_rna(float v) {
    float o;
    asm("cvt.rna.tf32.f32 %0, %1;" : "=f"(o) : "f"(v));
    return o;
}

// mma.sync m16n8k8 tf32: d += a * b  (family-neutral, works on sm_103)
__device__ __forceinline__ void mma_tf32(float* d,
    float a0, float a1, float a2, float a3, float b0, float b1)
{
    asm volatile(
        "mma.sync.aligned.m16n8k8.row.col.f32.tf32.tf32.f32 "
        "{%0,%1,%2,%3}, {%4,%5,%6,%7}, {%8,%9}, {%0,%1,%2,%3};"
        : "+f"(d[0]), "+f"(d[1]), "+f"(d[2]), "+f"(d[3])
        : "r"(__float_as_uint(a0)), "r"(__float_as_uint(a1)),
          "r"(__float_as_uint(a2)), "r"(__float_as_uint(a3)),
          "r"(__float_as_uint(b0)), "r"(__float_as_uint(b1)));
}

// ---------------------------------------------------------------------------
// Transpose: out[C][R] = in[R][C]
// ---------------------------------------------------------------------------
__global__ __launch_bounds__(256) void transpose_kernel(
    const float* __restrict__ in, float* __restrict__ out, int R, int C)
{
    __shared__ float t[32][33];
    const int c0 = blockIdx.x * 32, r0 = blockIdx.y * 32;
    const int x = threadIdx.x, y = threadIdx.y;  // 32 x 8
    #pragma unroll
    for (int i = 0; i < 32; i += 8)
        t[y + i][x] = in[(size_t)(r0 + y + i) * C + c0 + x];
    __syncthreads();
    #pragma unroll
    for (int i = 0; i < 32; i += 8)
        out[(size_t)(c0 + y + i) * R + r0 + x] = t[x][y + i];
}

// ---------------------------------------------------------------------------
// tf32 mma.sync GEMM: C[M,N] = A[M,K] @ Bt[N,K]^T
// BM=BN=128, BK=32. 256 threads = 8 warps (4 x 2), warp tile 32x64.
// Smem layout per tile row (32 floats): k-group j (8 cols), col 8j+c stored at
// float index 8j + 2*(c&3) + (c>>2)  -> (c, c+4) become an adjacent float2,
// matching tf32 m16n8k8 fragment pairs. Row stride 36 floats (pad).
// ---------------------------------------------------------------------------
#define GEMM_BUF_FLOATS (128 * 36)
#define GEMM_SMEM_BYTES (4 * GEMM_BUF_FLOATS * 4)   // A0,A1,B0,B1

__global__ __launch_bounds__(256) void gemm_tf32_mma_kernel(
    int M, int N, int K,
    const float* __restrict__ A, const float* __restrict__ Bt,
    float* __restrict__ C)
{
    extern __shared__ float sm[];
    float* sA = sm;                          // [2][128*36]
    float* sB = sm + 2 * GEMM_BUF_FLOATS;    // [2][128*36]

    const int tid  = threadIdx.x;
    const int wid  = tid >> 5, lane = tid & 31;
    const int tig  = lane & 3, grp = lane >> 2;
    const int wm   = wid & 3;        // 0..3 -> 32 rows each
    const int wn   = wid >> 2;       // 0..1 -> 64 cols each
    const int bm   = blockIdx.y * 128, bn = blockIdx.x * 128;

    float acc[2][8][4];
    #pragma unroll
    for (int mt = 0; mt < 2; ++mt)
        #pragma unroll
        for (int nt = 0; nt < 8; ++nt)
            #pragma unroll
            for (int e = 0; e < 4; ++e) acc[mt][nt][e] = 0.f;

    // loader indices: 1024 float4 per tile, 4 per thread
    const int lrow = tid >> 3;             // 0..31 (with +32*p)
    const int lc4  = (tid & 7) * 4;        // 0,4,...,28
    const int slot = 8 * (lc4 >> 3) + ((lc4 >> 2) & 1);  // base float slot

    float4 ra[4], rb[4];

    auto gload = [&](int it) {
        const int k0 = it * 32;
        #pragma unroll
        for (int p = 0; p < 4; ++p) {
            const int row = lrow + p * 32;
            ra[p] = *(const float4*)&A [(size_t)(bm + row) * K + k0 + lc4];
            rb[p] = *(const float4*)&Bt[(size_t)(bn + row) * K + k0 + lc4];
        }
    };
    auto sstore = [&](int buf) {
        float* dA = sA + buf * GEMM_BUF_FLOATS;
        float* dB = sB + buf * GEMM_BUF_FLOATS;
        #pragma unroll
        for (int p = 0; p < 4; ++p) {
            const int row = lrow + p * 32;
            float* pa = dA + row * 36 + slot;
            pa[0] = tf32_rna(ra[p].x); pa[2] = tf32_rna(ra[p].y);
            pa[4] = tf32_rna(ra[p].z); pa[6] = tf32_rna(ra[p].w);
            float* pb = dB + row * 36 + slot;
            pb[0] = tf32_rna(rb[p].x); pb[2] = tf32_rna(rb[p].y);
            pb[4] = tf32_rna(rb[p].z); pb[6] = tf32_rna(rb[p].w);
        }
    };

    const int NIT = K / 32;
    gload(0);
    sstore(0);

    for (int it = 0; it < NIT; ++it) {
        __syncthreads();
        if (it + 1 < NIT) gload(it + 1);

        const float* cA = sA + (it & 1) * GEMM_BUF_FLOATS;
        const float* cB = sB + (it & 1) * GEMM_BUF_FLOATS;
        #pragma unroll
        for (int j = 0; j < 4; ++j) {
            float2 af[2][2];
            #pragma unroll
            for (int mt = 0; mt < 2; ++mt) {
                const int r = wm * 32 + mt * 16 + grp;
                af[mt][0] = *(const float2*)&cA[r * 36 + 8 * j + 2 * tig];
                af[mt][1] = *(const float2*)&cA[(r + 8) * 36 + 8 * j + 2 * tig];
            }
            float2 bf[8];
            #pragma unroll
            for (int nt = 0; nt < 8; ++nt) {
                const int n = wn * 64 + nt * 8 + grp;
                bf[nt] = *(const float2*)&cB[n * 36 + 8 * j + 2 * tig];
            }
            #pragma unroll
            for (int mt = 0; mt < 2; ++mt)
                #pragma unroll
                for (int nt = 0; nt < 8; ++nt)
                    mma_tf32(acc[mt][nt],
                             af[mt][0].x, af[mt][1].x, af[mt][0].y, af[mt][1].y,
                             bf[nt].x, bf[nt].y);
        }

        if (it + 1 < NIT) {
            __syncthreads();
            sstore((it + 1) & 1);
        }
    }

    // epilogue
    #pragma unroll
    for (int mt = 0; mt < 2; ++mt) {
        const int m = bm + wm * 32 + mt * 16 + grp;
        #pragma unroll
        for (int nt = 0; nt < 8; ++nt) {
            const int n = bn + wn * 64 + nt * 8 + 2 * tig;
            float2 lo = {acc[mt][nt][0], acc[mt][nt][1]};
            float2 hi = {acc[mt][nt][2], acc[mt][nt][3]};
            *(float2*)&C[(size_t)m * N + n] = lo;
            *(float2*)&C[(size_t)(m + 8) * N + n] = hi;
        }
    }
}

// ---------------------------------------------------------------------------
// Fused RoPE + RMSNorm, in place. One warp per 128-dim vector.
// ---------------------------------------------------------------------------
__global__ __launch_bounds__(256) void rope_rms_kernel(
    float* __restrict__ v, const float* __restrict__ cosb,
    const float* __restrict__ sinb, int vecs_per_token)
{
    const int warp = (blockIdx.x * blockDim.x + threadIdx.x) >> 5;
    const int lane = threadIdx.x & 31;
    const int l = (warp / vecs_per_token) % L_;

    float* p = v + (size_t)warp * HD_;
    float e0 = p[lane];
    float e1 = p[lane + 32];
    float e2 = p[lane + 64];
    float e3 = p[lane + 96];
    float c0 = cosb[l * 64 + lane];
    float s0 = sinb[l * 64 + lane];
    float c1 = cosb[l * 64 + lane + 32];
    float s1 = sinb[l * 64 + lane + 32];

    float r0 =  e0 * c0 + e2 * s0;
    float r2 = -e0 * s0 + e2 * c0;
    float r1 =  e1 * c1 + e3 * s1;
    float r3 = -e1 * s1 + e3 * c1;

    float ss = r0 * r0 + r1 * r1 + r2 * r2 + r3 * r3;
    #pragma unroll
    for (int o = 16; o; o >>= 1) ss += __shfl_xor_sync(0xffffffffu, ss, o);
    float sc = rsqrtf(ss * (1.0f / 128.0f) + 1e-6f);

    p[lane]      = r0 * sc;
    p[lane + 32] = r1 * sc;
    p[lane + 64] = r2 * sc;
    p[lane + 96] = r3 * sc;
}

// ---------------------------------------------------------------------------
// Flash attention (causal, MQA), fp32 SIMT.
// ---------------------------------------------------------------------------
#define BQ 64
#define BKT 64
#define QS_STRIDE 132
#define SS_STRIDE 65
#define FLASH_SMEM_FLOATS (BQ*QS_STRIDE + HD_*BKT + BKT*HD_ + BQ*SS_STRIDE + 3*BQ)

__global__ __launch_bounds__(256) void flash_attn_kernel(
    const float* __restrict__ Q, const float* __restrict__ Kg,
    const float* __restrict__ Vg, float* __restrict__ Og)
{
    extern __shared__ float sm[];
    float* Qs   = sm;
    float* Kst  = Qs + BQ * QS_STRIDE;
    float* Vs   = Kst + HD_ * BKT;
    float* Ss   = Vs + BKT * HD_;
    float* mrow = Ss + BQ * SS_STRIDE;
    float* lrow = mrow + BQ;
    float* arow = lrow + BQ;

    const int q0 = blockIdx.x * BQ;
    const int h  = blockIdx.y;
    const int b  = blockIdx.z;
    const int tid = threadIdx.x;
    const int tx = tid & 15;
    const int ty = tid >> 4;

    for (int i = tid; i < BQ * HD_ / 4; i += 256) {
        int r = i >> 5, c4 = (i & 31) << 2;
        float4 v = *(const float4*)&Q[(((size_t)b * L_ + q0 + r) * H_ + h) * HD_ + c4];
        *(float4*)&Qs[r * QS_STRIDE + c4] = v;
    }
    if (tid < BQ) { mrow[tid] = -1e30f; lrow[tid] = 0.f; }
    __syncthreads();

    float o[4][8] = {};
    const float scale = 0.08838834764831843f;
    const int ntiles = q0 / BKT + 1;

    for (int t = 0; t < ntiles; ++t) {
        const int k0 = t * BKT;
        for (int i = tid; i < BKT * HD_ / 4; i += 256) {
            int r = i >> 5, c4 = (i & 31) << 2;
            float4 kv = *(const float4*)&Kg[((size_t)b * L_ + k0 + r) * HD_ + c4];
            Kst[(c4 + 0) * BKT + r] = kv.x;
            Kst[(c4 + 1) * BKT + r] = kv.y;
            Kst[(c4 + 2) * BKT + r] = kv.z;
            Kst[(c4 + 3) * BKT + r] = kv.w;
            float4 vv = *(const float4*)&Vg[((size_t)b * L_ + k0 + r) * HD_ + c4];
            *(float4*)&Vs[r * HD_ + c4] = vv;
        }
        __syncthreads();

        float s[4][4] = {};
        for (int d = 0; d < HD_; ++d) {
            float4 kr = *(const float4*)&Kst[d * BKT + tx * 4];
            float q0v = Qs[(ty * 4 + 0) * QS_STRIDE + d];
            float q1v = Qs[(ty * 4 + 1) * QS_STRIDE + d];
            float q2v = Qs[(ty * 4 + 2) * QS_STRIDE + d];
            float q3v = Qs[(ty * 4 + 3) * QS_STRIDE + d];
            s[0][0] += q0v * kr.x; s[0][1] += q0v * kr.y; s[0][2] += q0v * kr.z; s[0][3] += q0v * kr.w;
            s[1][0] += q1v * kr.x; s[1][1] += q1v * kr.y; s[1][2] += q1v * kr.z; s[1][3] += q1v * kr.w;
            s[2][0] += q2v * kr.x; s[2][1] += q2v * kr.y; s[2][2] += q2v * kr.z; s[2][3] += q2v * kr.w;
            s[3][0] += q3v * kr.x; s[3][1] += q3v * kr.y; s[3][2] += q3v * kr.z; s[3][3] += q3v * kr.w;
        }

        #pragma unroll
        for (int i = 0; i < 4; ++i) {
            const int qi = q0 + ty * 4 + i;
            #pragma unroll
            for (int j = 0; j < 4; ++j) {
                const int kj = k0 + tx * 4 + j;
                Ss[(ty * 4 + i) * SS_STRIDE + tx * 4 + j] =
                    (kj <= qi) ? s[i][j] * scale : -1e30f;
            }
        }
        __syncthreads();

        if (tid < BQ) {
            float m_old = mrow[tid];
            float mx = m_old;
            #pragma unroll 4
            for (int j = 0; j < BKT; ++j) mx = fmaxf(mx, Ss[tid * SS_STRIDE + j]);
            float sum = 0.f;
            #pragma unroll 4
            for (int j = 0; j < BKT; ++j) {
                float pv = __expf(Ss[tid * SS_STRIDE + j] - mx);
                Ss[tid * SS_STRIDE + j] = pv;
                sum += pv;
            }
            float alpha = __expf(m_old - mx);
            lrow[tid] = lrow[tid] * alpha + sum;
            mrow[tid] = mx;
            arow[tid] = alpha;
        }
        __syncthreads();

        #pragma unroll
        for (int i = 0; i < 4; ++i) {
            float alpha = arow[ty * 4 + i];
            #pragma unroll
            for (int j = 0; j < 8; ++j) o[i][j] *= alpha;
        }
        for (int kk = 0; kk < BKT; ++kk) {
            float4 v0 = *(const float4*)&Vs[kk * HD_ + tx * 4];
            float4 v1 = *(const float4*)&Vs[kk * HD_ + 64 + tx * 4];
            #pragma unroll
            for (int i = 0; i < 4; ++i) {
                float pv = Ss[(ty * 4 + i) * SS_STRIDE + kk];
                o[i][0] += pv * v0.x; o[i][1] += pv * v0.y;
                o[i][2] += pv * v0.z; o[i][3] += pv * v0.w;
                o[i][4] += pv * v1.x; o[i][5] += pv * v1.y;
                o[i][6] += pv * v1.z; o[i][7] += pv * v1.w;
            }
        }
        __syncthreads();
    }

    #pragma unroll
    for (int i = 0; i < 4; ++i) {
        const int row = q0 + ty * 4 + i;
        const float inv = 1.f / lrow[ty * 4 + i];
        float4 r0 = {o[i][0]*inv, o[i][1]*inv, o[i][2]*inv, o[i][3]*inv};
        float4 r1 = {o[i][4]*inv, o[i][5]*inv, o[i][6]*inv, o[i][7]*inv};
        size_t base = ((size_t)b * L_ + row) * DIM_ + (size_t)h * HD_;
        *(float4*)&Og[base + tx * 4] = r0;
        *(float4*)&Og[base + 64 + tx * 4] = r1;
    }
}

// ---------------------------------------------------------------------------
extern "C" void kernel_launch(void* const* d_in, const int* in_sizes, int n_in,
                              void* d_out, int out_size)
{
    const float* x    = (const float*)d_in[0];
    const float* cosb = (const float*)d_in[1];
    const float* sinb = (const float*)d_in[2];
    const float* Wq   = (const float*)d_in[3];
    const float* Wk   = (const float*)d_in[4];
    const float* Wv   = (const float*)d_in[5];
    const float* Wo   = (const float*)d_in[6];
    float* out = (float*)d_out;

    float *qp, *kp, *vp, *aop, *wqt, *wot, *wkt, *wvt;
    cudaGetSymbolAddress((void**)&qp, g_q);
    cudaGetSymbolAddress((void**)&kp, g_k);
    cudaGetSymbolAddress((void**)&vp, g_v);
    cudaGetSymbolAddress((void**)&aop, g_ao);
    cudaGetSymbolAddress((void**)&wqt, g_wqt);
    cudaGetSymbolAddress((void**)&wot, g_wot);
    cudaGetSymbolAddress((void**)&wkt, g_wkt);
    cudaGetSymbolAddress((void**)&wvt, g_wvt);

    const int M = B_ * L_;   // 4096

    cudaFuncSetAttribute(gemm_tf32_mma_kernel,
                         cudaFuncAttributeMaxDynamicSharedMemorySize, GEMM_SMEM_BYTES);

    // 0) transpose weights to [N][K]
    transpose_kernel<<<dim3(DIM_/32, DIM_/32), dim3(32,8)>>>(Wq, wqt, DIM_, DIM_);
    transpose_kernel<<<dim3(HD_/32,  DIM_/32), dim3(32,8)>>>(Wk, wkt, DIM_, HD_);
    transpose_kernel<<<dim3(HD_/32,  DIM_/32), dim3(32,8)>>>(Wv, wvt, DIM_, HD_);
    transpose_kernel<<<dim3(DIM_/32, DIM_/32), dim3(32,8)>>>(Wo, wot, DIM_, DIM_);

    // 1) projections via mma.sync tf32
    gemm_tf32_mma_kernel<<<dim3(DIM_/128, M/128), 256, GEMM_SMEM_BYTES>>>(M, DIM_, DIM_, x, wqt, qp);
    gemm_tf32_mma_kernel<<<dim3(1,        M/128), 256, GEMM_SMEM_BYTES>>>(M, HD_,  DIM_, x, wkt, kp);
    gemm_tf32_mma_kernel<<<dim3(1,        M/128), 256, GEMM_SMEM_BYTES>>>(M, HD_,  DIM_, x, wvt, vp);

    // 2) RoPE + RMSNorm
    rope_rms_kernel<<<(M * H_) * 32 / 256, 256>>>(qp, cosb, sinb, H_);
    rope_rms_kernel<<<M * 32 / 256, 256>>>(kp, cosb, sinb, 1);

    // 3) causal MQA flash attention (fp32 SIMT)
    const size_t smem = FLASH_SMEM_FLOATS * sizeof(float);
    cudaFuncSetAttribute(flash_attn_kernel,
                         cudaFuncAttributeMaxDynamicSharedMemorySize, (int)smem);
    flash_attn_kernel<<<dim3(L_ / BQ, H_, B_), 256, smem>>>(qp, kp, vp, aop);

    // 4) output projection
    gemm_tf32_mma_kernel<<<dim3(DIM_/128, M/128), 256, GEMM_SMEM_BYTES>>>(M, DIM_, DIM_, aop, wot, out);
}

// round 5
// speedup vs baseline: 6.8014x; 5.0656x over previous
#include <cuda_runtime.h>
#include <cuda_fp16.h>
#include <cstdint>
#include <math.h>

#define B_  2
#define L_  2048
#define DIM_ 2048
#define H_  16
#define HD_ 128

// ---------------------------------------------------------------------------
// Scratch (device globals)
// ---------------------------------------------------------------------------
__device__ __half g_xh  [(size_t)B_ * L_ * DIM_];   // x in half
__device__ __half g_wqt [(size_t)DIM_ * DIM_];      // Wq^T half [N][K]
__device__ __half g_wot [(size_t)DIM_ * DIM_];      // Wo^T half
__device__ __half g_wkvt[(size_t)256 * DIM_];       // [Wk^T ; Wv^T] half
__device__ __half g_qp  [(size_t)B_ * L_ * DIM_];   // q proj (roped in place)
__device__ __half g_kv  [(size_t)B_ * L_ * 256];    // k|v proj (k roped in place)
__device__ __half g_aoh [(size_t)B_ * L_ * DIM_];   // attention out half

// ---------------------------------------------------------------------------
// PTX helpers
// ---------------------------------------------------------------------------
__device__ __forceinline__ uint32_t smem_u32(const void* p) {
    uint32_t a;
    asm("{ .reg .u64 t; cvta.to.shared.u64 t, %1; cvt.u32.u64 %0, t; }"
        : "=r"(a) : "l"(p));
    return a;
}
__device__ __forceinline__ void cp16(uint32_t dst, const void* src) {
    asm volatile("cp.async.cg.shared.global [%0], [%1], 16;" :: "r"(dst), "l"(src));
}
#define CP_COMMIT() asm volatile("cp.async.commit_group;")
#define CP_WAIT(n)  asm volatile("cp.async.wait_group %0;" :: "n"(n))

__device__ __forceinline__ void ldsm_x4(uint32_t* r, uint32_t addr) {
    asm volatile("ldmatrix.sync.aligned.m8n8.x4.shared.b16 {%0,%1,%2,%3}, [%4];"
        : "=r"(r[0]), "=r"(r[1]), "=r"(r[2]), "=r"(r[3]) : "r"(addr));
}
__device__ __forceinline__ void ldsm_x4_t(uint32_t* r, uint32_t addr) {
    asm volatile("ldmatrix.sync.aligned.m8n8.x4.trans.shared.b16 {%0,%1,%2,%3}, [%4];"
        : "=r"(r[0]), "=r"(r[1]), "=r"(r[2]), "=r"(r[3]) : "r"(addr));
}
__device__ __forceinline__ void mma16(float* d, const uint32_t* a,
                                      uint32_t b0, uint32_t b1) {
    asm volatile(
        "mma.sync.aligned.m16n8k16.row.col.f32.f16.f16.f32 "
        "{%0,%1,%2,%3}, {%4,%5,%6,%7}, {%8,%9}, {%0,%1,%2,%3};"
        : "+f"(d[0]), "+f"(d[1]), "+f"(d[2]), "+f"(d[3])
        : "r"(a[0]), "r"(a[1]), "r"(a[2]), "r"(a[3]), "r"(b0), "r"(b1));
}
__device__ __forceinline__ uint32_t pkh2(float lo, float hi) {
    uint32_t r;
    asm("cvt.rn.f16x2.f32 %0, %1, %2;" : "=r"(r) : "f"(hi), "f"(lo));
    return r;
}

// ---------------------------------------------------------------------------
// f32 -> half conversion (float4 granularity)
// ---------------------------------------------------------------------------
__global__ __launch_bounds__(256) void f2h_kernel(
    const float* __restrict__ in, __half* __restrict__ out, int n4)
{
    int i = blockIdx.x * blockDim.x + threadIdx.x;
    if (i < n4) {
        float4 v = ((const float4*)in)[i];
        ((uint2*)out)[i] = make_uint2(pkh2(v.x, v.y), pkh2(v.z, v.w));
    }
}

// ---------------------------------------------------------------------------
// Transpose f32 -> half: out[c][r] = in[r][c]
// ---------------------------------------------------------------------------
__global__ __launch_bounds__(256) void transpose_h_kernel(
    const float* __restrict__ in, __half* __restrict__ out,
    int R, int C, int ostride)
{
    __shared__ float t[32][33];
    const int c0 = blockIdx.x * 32, r0 = blockIdx.y * 32;
    const int x = threadIdx.x, y = threadIdx.y;  // 32 x 8
    #pragma unroll
    for (int i = 0; i < 32; i += 8)
        t[y + i][x] = in[(size_t)(r0 + y + i) * C + c0 + x];
    __syncthreads();
    #pragma unroll
    for (int i = 0; i < 32; i += 8)
        out[(size_t)(c0 + y + i) * ostride + r0 + x] = __float2half_rn(t[x][y + i]);
}

// ---------------------------------------------------------------------------
// fp16 mma GEMM: C[M,N] = A[M,K] * Bt[N,K]^T.  BM=BN=128, BK=32, 4-stage
// cp.async, 256 threads = 8 warps (4m x 2n), warp tile 32x64.
// smem row: 32 halves = 4 chunks of 16B, 80B row stride (conflict-free).
// ---------------------------------------------------------------------------
#define G_STG_B 10240           // 128 rows * 80B
#define GEMM_SMEM (4 * 2 * G_STG_B)

template<bool OUT_HALF>
__global__ __launch_bounds__(256) void gemm16_kernel(
    int M, int N, int K,
    const __half* __restrict__ A, const __half* __restrict__ Bt, void* Cout)
{
    extern __shared__ char smem[];
    const uint32_t sA = smem_u32(smem);
    const uint32_t sB = sA + 4 * G_STG_B;

    const int tid = threadIdx.x, wid = tid >> 5, lane = tid & 31;
    const int grp = lane >> 2, tig = lane & 3;
    const int lrow = lane & 15, lhi = lane >> 4;
    const int wm = wid & 3, wn = wid >> 2;
    const int bm = blockIdx.y * 128, bn = blockIdx.x * 128;

    float acc[2][8][4];
    #pragma unroll
    for (int mt = 0; mt < 2; ++mt)
        #pragma unroll
        for (int nb = 0; nb < 8; ++nb)
            #pragma unroll
            for (int e = 0; e < 4; ++e) acc[mt][nb][e] = 0.f;

    const int ld_row = tid >> 1, ld_ch = (tid & 1) * 2;
    const __half* Asrc = A  + (size_t)(bm + ld_row) * K + ld_ch * 8;
    const __half* Bsrc = Bt + (size_t)(bn + ld_row) * K + ld_ch * 8;
    const uint32_t Adst = sA + ld_row * 80 + ld_ch * 16;
    const uint32_t Bdst = sB + ld_row * 80 + ld_ch * 16;

    auto issue = [&](int it, int stg) {
        const __half* as = Asrc + it * 32;
        const __half* bs = Bsrc + it * 32;
        uint32_t ad = Adst + stg * G_STG_B;
        uint32_t bd = Bdst + stg * G_STG_B;
        cp16(ad, as); cp16(ad + 16, as + 8);
        cp16(bd, bs); cp16(bd + 16, bs + 8);
    };

    const int NIT = K / 32;
    issue(0, 0); CP_COMMIT();
    issue(1, 1); CP_COMMIT();
    issue(2, 2); CP_COMMIT();

    const uint32_t offA0 = (wm * 32 + lrow) * 80 + lhi * 16;
    const uint32_t offB0 = (wn * 64 + lrow) * 80 + lhi * 16;

    for (int it = 0; it < NIT; ++it) {
        CP_WAIT(2);
        __syncthreads();
        if (it + 3 < NIT) issue(it + 3, (it + 3) & 3);
        CP_COMMIT();

        const uint32_t cA = sA + (it & 3) * G_STG_B + offA0;
        const uint32_t cB = sB + (it & 3) * G_STG_B + offB0;
        #pragma unroll
        for (int ks = 0; ks < 2; ++ks) {
            uint32_t a[2][4];
            ldsm_x4(a[0], cA + ks * 32);
            ldsm_x4(a[1], cA + 16 * 80 + ks * 32);
            #pragma unroll
            for (int j = 0; j < 4; ++j) {
                uint32_t bb[4];
                ldsm_x4(bb, cB + j * 16 * 80 + ks * 32);
                #pragma unroll
                for (int mt = 0; mt < 2; ++mt) {
                    mma16(acc[mt][2 * j],     a[mt], bb[0], bb[2]);
                    mma16(acc[mt][2 * j + 1], a[mt], bb[1], bb[3]);
                }
            }
        }
    }

    #pragma unroll
    for (int mt = 0; mt < 2; ++mt) {
        const int m = bm + wm * 32 + mt * 16 + grp;
        #pragma unroll
        for (int nb = 0; nb < 8; ++nb) {
            const int n = bn + wn * 64 + nb * 8 + 2 * tig;
            if (OUT_HALF) {
                __half* C = (__half*)Cout;
                *(uint32_t*)&C[(size_t)m * N + n] = pkh2(acc[mt][nb][0], acc[mt][nb][1]);
                *(uint32_t*)&C[(size_t)(m + 8) * N + n] = pkh2(acc[mt][nb][2], acc[mt][nb][3]);
            } else {
                float* C = (float*)Cout;
                *(float2*)&C[(size_t)m * N + n] = make_float2(acc[mt][nb][0], acc[mt][nb][1]);
                *(float2*)&C[(size_t)(m + 8) * N + n] = make_float2(acc[mt][nb][2], acc[mt][nb][3]);
            }
        }
    }
}

// ---------------------------------------------------------------------------
// Fused RoPE + RMSNorm, half in/out, in place. One warp per 128-dim vector.
// p = buf + vec*vstride ; l = (vec/vpt) % L_
// ---------------------------------------------------------------------------
__global__ __launch_bounds__(256) void rope16_kernel(
    __half* __restrict__ buf, int vstride, int vpt,
    const float* __restrict__ cosb, const float* __restrict__ sinb)
{
    const int vec = (blockIdx.x * blockDim.x + threadIdx.x) >> 5;
    const int lane = threadIdx.x & 31;
    const int l = (vec / vpt) % L_;

    __half* p = buf + (size_t)vec * vstride;
    float e0 = __half2float(p[lane]);
    float e1 = __half2float(p[lane + 32]);
    float e2 = __half2float(p[lane + 64]);
    float e3 = __half2float(p[lane + 96]);
    float c0 = cosb[l * 64 + lane];
    float s0 = sinb[l * 64 + lane];
    float c1 = cosb[l * 64 + lane + 32];
    float s1 = sinb[l * 64 + lane + 32];

    float r0 =  e0 * c0 + e2 * s0;
    float r2 = -e0 * s0 + e2 * c0;
    float r1 =  e1 * c1 + e3 * s1;
    float r3 = -e1 * s1 + e3 * c1;

    float ss = r0 * r0 + r1 * r1 + r2 * r2 + r3 * r3;
    #pragma unroll
    for (int o = 16; o; o >>= 1) ss += __shfl_xor_sync(0xffffffffu, ss, o);
    float sc = rsqrtf(ss * (1.0f / 128.0f) + 1e-6f);

    p[lane]      = __float2half_rn(r0 * sc);
    p[lane + 32] = __float2half_rn(r1 * sc);
    p[lane + 64] = __float2half_rn(r2 * sc);
    p[lane + 96] = __float2half_rn(r3 * sc);
}

// ---------------------------------------------------------------------------
// fp16 flash attention (causal MQA). BQ=128 rows/CTA, key tiles of 64,
// 8 warps each owning a 16-row band. Double-buffered cp.async K/V.
// smem row stride 272B (conflict-free for ldmatrix).
// ---------------------------------------------------------------------------
#define FL_SMEM (128*272 + 4*64*272)    // Q + 2*(K+V) = 104448

__global__ __launch_bounds__(256) void flash16_kernel(
    const __half* __restrict__ qh, const __half* __restrict__ kvh,
    __half* __restrict__ aoh)
{
    extern __shared__ char smem[];
    const uint32_t sQ = smem_u32(smem);
    const uint32_t sKV = sQ + 128 * 272;   // [2 bufs][K 64 rows | V 64 rows]

    const int tid = threadIdx.x, w = tid >> 5, lane = tid & 31;
    const int grp = lane >> 2, tig = lane & 3;
    const int lrow = lane & 15, lhi = lane >> 4;
    const int qx = gridDim.x - 1 - blockIdx.x;     // heavy blocks first
    const int q0 = qx * 128, h = blockIdx.y, b = blockIdx.z;

    // Q tile 128x128
    {
        const int row = tid >> 1, c0 = (tid & 1) * 8;
        const __half* src = qh + (((size_t)(b * L_ + q0 + row)) * H_ + h) * HD_ + c0 * 8;
        const uint32_t dst = sQ + row * 272 + c0 * 16;
        #pragma unroll
        for (int c = 0; c < 8; ++c) cp16(dst + c * 16, src + c * 8);
    }
    const int kvrow = tid >> 2, kvc = (tid & 3) * 4;
    auto issue_kv = [&](int k0, int buf) {
        const __half* base = kvh + (size_t)(b * L_ + k0 + kvrow) * 256 + kvc * 8;
        const uint32_t kd = sKV + buf * (2 * 64 * 272) + kvrow * 272 + kvc * 16;
        const uint32_t vd = kd + 64 * 272;
        #pragma unroll
        for (int c = 0; c < 4; ++c) {
            cp16(kd + c * 16, base + c * 8);          // k: cols 0..127
            cp16(vd + c * 16, base + 128 + c * 8);    // v: cols 128..255
        }
    };
    issue_kv(0, 0); CP_COMMIT(); CP_WAIT(0); __syncthreads();

    float m0 = -1e30f, m1 = -1e30f, l0 = 0.f, l1 = 0.f;
    float o[16][4];
    #pragma unroll
    for (int d = 0; d < 16; ++d)
        #pragma unroll
        for (int e = 0; e < 4; ++e) o[d][e] = 0.f;

    const float sc = 0.08838834764831843f * 1.4426950408889634f;  // scale*log2e
    const int ntiles = q0 / 64 + 2;
    const int wrow = q0 + w * 16;

    for (int t = 0; t < ntiles; ++t) {
        const int k0 = t * 64;
        if (t + 1 < ntiles) { issue_kv(k0 + 64, (t + 1) & 1); CP_COMMIT(); }

        const uint32_t cK = sKV + (t & 1) * (2 * 64 * 272);
        const uint32_t cV = cK + 64 * 272;

        if (k0 <= wrow + 15) {
            float s[8][4];
            #pragma unroll
            for (int nb = 0; nb < 8; ++nb)
                #pragma unroll
                for (int e = 0; e < 4; ++e) s[nb][e] = 0.f;

            #pragma unroll
            for (int ks = 0; ks < 8; ++ks) {
                uint32_t a[4];
                ldsm_x4(a, sQ + (w * 16 + lrow) * 272 + (2 * ks + lhi) * 16);
                #pragma unroll
                for (int j = 0; j < 4; ++j) {
                    uint32_t bb[4];
                    ldsm_x4(bb, cK + (j * 16 + lrow) * 272 + (2 * ks + lhi) * 16);
                    mma16(s[2 * j],     a, bb[0], bb[2]);
                    mma16(s[2 * j + 1], a, bb[1], bb[3]);
                }
            }
            #pragma unroll
            for (int nb = 0; nb < 8; ++nb)
                #pragma unroll
                for (int e = 0; e < 4; ++e) s[nb][e] *= sc;
            if (k0 + 63 > wrow) {          // diagonal tile: mask
                const int r0g = wrow + grp, r1g = r0g + 8;
                #pragma unroll
                for (int nb = 0; nb < 8; ++nb) {
                    const int cg = k0 + nb * 8 + 2 * tig;
                    if (cg     > r0g) s[nb][0] = -1e30f;
                    if (cg + 1 > r0g) s[nb][1] = -1e30f;
                    if (cg     > r1g) s[nb][2] = -1e30f;
                    if (cg + 1 > r1g) s[nb][3] = -1e30f;
                }
            }
            float mx0 = -1e30f, mx1 = -1e30f;
            #pragma unroll
            for (int nb = 0; nb < 8; ++nb) {
                mx0 = fmaxf(mx0, fmaxf(s[nb][0], s[nb][1]));
                mx1 = fmaxf(mx1, fmaxf(s[nb][2], s[nb][3]));
            }
            mx0 = fmaxf(mx0, __shfl_xor_sync(0xffffffffu, mx0, 1));
            mx0 = fmaxf(mx0, __shfl_xor_sync(0xffffffffu, mx0, 2));
            mx1 = fmaxf(mx1, __shfl_xor_sync(0xffffffffu, mx1, 1));
            mx1 = fmaxf(mx1, __shfl_xor_sync(0xffffffffu, mx1, 2));
            const float mn0 = fmaxf(m0, mx0), mn1 = fmaxf(m1, mx1);
            const float al0 = exp2f(m0 - mn0), al1 = exp2f(m1 - mn1);
            m0 = mn0; m1 = mn1;

            float sum0 = 0.f, sum1 = 0.f;
            #pragma unroll
            for (int nb = 0; nb < 8; ++nb) {
                s[nb][0] = exp2f(s[nb][0] - mn0); sum0 += s[nb][0];
                s[nb][1] = exp2f(s[nb][1] - mn0); sum0 += s[nb][1];
                s[nb][2] = exp2f(s[nb][2] - mn1); sum1 += s[nb][2];
                s[nb][3] = exp2f(s[nb][3] - mn1); sum1 += s[nb][3];
            }
            sum0 += __shfl_xor_sync(0xffffffffu, sum0, 1);
            sum0 += __shfl_xor_sync(0xffffffffu, sum0, 2);
            sum1 += __shfl_xor_sync(0xffffffffu, sum1, 1);
            sum1 += __shfl_xor_sync(0xffffffffu, sum1, 2);
            l0 = l0 * al0 + sum0;
            l1 = l1 * al1 + sum1;

            // P -> A fragments (registers only; C layout == A layout)
            uint32_t pa[4][4];
            #pragma unroll
            for (int kp = 0; kp < 4; ++kp) {
                pa[kp][0] = pkh2(s[2 * kp][0],     s[2 * kp][1]);
                pa[kp][1] = pkh2(s[2 * kp][2],     s[2 * kp][3]);
                pa[kp][2] = pkh2(s[2 * kp + 1][0], s[2 * kp + 1][1]);
                pa[kp][3] = pkh2(s[2 * kp + 1][2], s[2 * kp + 1][3]);
            }
            #pragma unroll
            for (int d = 0; d < 16; ++d) {
                o[d][0] *= al0; o[d][1] *= al0;
                o[d][2] *= al1; o[d][3] *= al1;
            }
            // O += P @ V (ldmatrix.trans on row-major V)
            #pragma unroll
            for (int kp = 0; kp < 4; ++kp)
                #pragma unroll
                for (int j = 0; j < 8; ++j) {
                    uint32_t vv[4];
                    ldsm_x4_t(vv, cV + (kp * 16 + lrow) * 272 + (2 * j + lhi) * 16);
                    mma16(o[2 * j],     pa[kp], vv[0], vv[1]);
                    mma16(o[2 * j + 1], pa[kp], vv[2], vv[3]);
                }
        }
        if (t + 1 < ntiles) { CP_WAIT(0); __syncthreads(); }
    }

    // epilogue
    const float inv0 = 1.f / l0, inv1 = 1.f / l1;
    const int r0g = q0 + w * 16 + grp;
    __half* op0 = aoh + (size_t)(b * L_ + r0g) * DIM_ + h * HD_;
    __half* op1 = op0 + (size_t)8 * DIM_;
    #pragma unroll
    for (int d = 0; d < 16; ++d) {
        const int col = d * 8 + 2 * tig;
        *(uint32_t*)(op0 + col) = pkh2(o[d][0] * inv0, o[d][1] * inv0);
        *(uint32_t*)(op1 + col) = pkh2(o[d][2] * inv1, o[d][3] * inv1);
    }
}

// ---------------------------------------------------------------------------
extern "C" void kernel_launch(void* const* d_in, const int* in_sizes, int n_in,
                              void* d_out, int out_size)
{
    const float* x    = (const float*)d_in[0];
    const float* cosb = (const float*)d_in[1];
    const float* sinb = (const float*)d_in[2];
    const float* Wq   = (const float*)d_in[3];
    const float* Wk   = (const float*)d_in[4];
    const float* Wv   = (const float*)d_in[5];
    const float* Wo   = (const float*)d_in[6];
    float* out = (float*)d_out;

    __half *xh, *wqt, *wot, *wkvt, *qp, *kv, *aoh;
    cudaGetSymbolAddress((void**)&xh,   g_xh);
    cudaGetSymbolAddress((void**)&wqt,  g_wqt);
    cudaGetSymbolAddress((void**)&wot,  g_wot);
    cudaGetSymbolAddress((void**)&wkvt, g_wkvt);
    cudaGetSymbolAddress((void**)&qp,   g_qp);
    cudaGetSymbolAddress((void**)&kv,   g_kv);
    cudaGetSymbolAddress((void**)&aoh,  g_aoh);

    const int M = B_ * L_;   // 4096

    cudaFuncSetAttribute(gemm16_kernel<true>,
                         cudaFuncAttributeMaxDynamicSharedMemorySize, GEMM_SMEM);
    cudaFuncSetAttribute(gemm16_kernel<false>,
                         cudaFuncAttributeMaxDynamicSharedMemorySize, GEMM_SMEM);
    cudaFuncSetAttribute(flash16_kernel,
                         cudaFuncAttributeMaxDynamicSharedMemorySize, FL_SMEM);

    // 0) convert x to half; transpose weights to half [N][K]
    f2h_kernel<<<(M * DIM_ / 4 + 255) / 256, 256>>>(x, xh, M * DIM_ / 4);
    transpose_h_kernel<<<dim3(DIM_/32, DIM_/32), dim3(32,8)>>>(Wq, wqt, DIM_, DIM_, DIM_);
    transpose_h_kernel<<<dim3(HD_/32,  DIM_/32), dim3(32,8)>>>(Wk, wkvt, DIM_, HD_, DIM_);
    transpose_h_kernel<<<dim3(HD_/32,  DIM_/32), dim3(32,8)>>>(Wv, wkvt + (size_t)128 * DIM_, DIM_, HD_, DIM_);
    transpose_h_kernel<<<dim3(DIM_/32, DIM_/32), dim3(32,8)>>>(Wo, wot, DIM_, DIM_, DIM_);

    // 1) projections (fp16 mma)
    gemm16_kernel<true><<<dim3(DIM_/128, M/128), 256, GEMM_SMEM>>>(M, DIM_, DIM_, xh, wqt, qp);
    gemm16_kernel<true><<<dim3(256/128,  M/128), 256, GEMM_SMEM>>>(M, 256,  DIM_, xh, wkvt, kv);

    // 2) RoPE + RMSNorm in place (q: 65536 vecs, k: 4096 vecs)
    rope16_kernel<<<M * H_ / 8, 256>>>(qp, 128, 16, cosb, sinb);
    rope16_kernel<<<M / 8, 256>>>(kv, 256, 1, cosb, sinb);

    // 3) fp16 flash attention
    flash16_kernel<<<dim3(L_/128, H_, B_), 256, FL_SMEM>>>(qp, kv, aoh);

    // 4) output projection (float out)
    gemm16_kernel<false><<<dim3(DIM_/128, M/128), 256, GEMM_SMEM>>>(M, DIM_, DIM_, aoh, wot, out);
}